// round 17
// baseline (speedup 1.0000x reference)
#include <cuda_runtime.h>

#define NN 100000
#define EE 1600000
#define SCAN_NB 196     // ceil(NN/512)
#define GEMM_NB 782     // ceil(NN/128)
#define SCAT_NB 3125    // ceil(EE/512)

// ---------------- scratch (device globals; no allocation) ----------------
__device__ __align__(256) float g_feat1[NN * 128]; // layer1 features [N][H=4][D=32]
__device__ __align__(16)  float g_el1[NN * 4];
__device__ __align__(16)  float g_er1[NN * 4];
__device__ __align__(16) float g_feat2[NN * 16];
__device__ float g_el2[NN];
__device__ float g_er2[NN];
__device__ int   g_rowptr[NN + 1];
__device__ int   g_cursor[NN];        // zero at start of each call (BSS / node2 cleanup)
__device__ int   g_csrsrc[EE];
__device__ unsigned long long g_desc[SCAN_NB];  // lookback: flag<<32 | value
__device__ int   g_scanctr;

// ---------------- f32x2 packed FMA (Blackwell) ----------------
__device__ __forceinline__ unsigned long long ffma2(unsigned long long a,
                                                    unsigned long long b,
                                                    unsigned long long c) {
    unsigned long long d;
    asm("fma.rn.f32x2 %0, %1, %2, %3;" : "=l"(d) : "l"(a), "l"(b), "l"(c));
    return d;
}

__device__ __forceinline__ void cpasync16(unsigned int dst, const void* src, int srcbytes) {
    asm volatile("cp.async.cg.shared.global [%0], [%1], 16, %2;"
                 :: "r"(dst), "l"(src), "r"(srcbytes));
}
__device__ __forceinline__ void cpasync_commit() {
    asm volatile("cp.async.commit_group;");
}

// ---------------- histogram of dst ----------------
__global__ void hist_kernel(const int* __restrict__ dst) {
    int e = blockIdx.x * 256 + threadIdx.x;
    if (e < EE) atomicAdd(&g_cursor[dst[e]], 1);
}

// ---------------- single-pass exclusive scan (decoupled lookback) ---------
__global__ void __launch_bounds__(256) scan_kernel() {
    __shared__ int sh[256];
    __shared__ int s_bid;
    __shared__ int s_prefix;
    int t = threadIdx.x;
    if (t == 0) s_bid = atomicAdd(&g_scanctr, 1);
    __syncthreads();
    int b = s_bid;
    if (t == 0 && b == 0) g_rowptr[NN] = EE;
    int i0 = b * 512 + 2 * t;
    int c0 = (i0 < NN) ? g_cursor[i0] : 0;
    int c1 = (i0 + 1 < NN) ? g_cursor[i0 + 1] : 0;
    int local = c0 + c1;
    sh[t] = local;
    __syncthreads();
    for (int o = 1; o < 256; o <<= 1) {
        int v = (t >= o) ? sh[t - o] : 0;
        __syncthreads();
        sh[t] += v;
        __syncthreads();
    }
    int total = sh[255];
    if (t == 0) {
        if (b == 0) {
            *(volatile unsigned long long*)&g_desc[0] =
                (2ULL << 32) | (unsigned long long)(unsigned)total;
            s_prefix = 0;
        } else {
            *(volatile unsigned long long*)&g_desc[b] =
                (1ULL << 32) | (unsigned long long)(unsigned)total;
            int prefix = 0;
            int j = b - 1;
            while (true) {
                unsigned long long dsc;
                do { dsc = *(volatile unsigned long long*)&g_desc[j]; } while ((dsc >> 32) == 0ULL);
                prefix += (int)(unsigned)dsc;
                if ((dsc >> 32) == 2ULL) break;
                j--;
            }
            *(volatile unsigned long long*)&g_desc[b] =
                (2ULL << 32) | (unsigned long long)(unsigned)(prefix + total);
            s_prefix = prefix;
        }
    }
    __syncthreads();
    int off = s_prefix + sh[t] - local;
    if (i0 < NN)     { g_rowptr[i0] = off;          g_cursor[i0] = off; }
    if (i0 + 1 < NN) { g_rowptr[i0 + 1] = off + c0; g_cursor[i0 + 1] = off + c0; }
}

// ---------------- fused GEMM1 (+coef epilogue) and CSR scatter ------------
// 512 threads. blocks [0, GEMM_NB): 128x128 tile of feat1 = x @ W1, thread
// tile 4 rows x 8 cols (4 f32x2), cp.async double-buffered k-tiles of 16.
// blocks [GEMM_NB, +SCAT_NB): scatter edges into CSR (overlaps on SM).
__global__ void __launch_bounds__(512) gemm1_scatter_kernel(
        const float* __restrict__ x, const float* __restrict__ W,
        const float* __restrict__ al1, const float* __restrict__ ar1,
        const int* __restrict__ src, const int* __restrict__ dst) {

    if (blockIdx.x >= GEMM_NB) {
        int e = (blockIdx.x - GEMM_NB) * 512 + threadIdx.x;
        if (e < EE) {
            int d = dst[e];
            int slot = atomicAdd(&g_cursor[d], 1);
            g_csrsrc[slot] = src[e];
        }
        return;
    }

    __shared__ float As[2][128 * 16];   // [buf][row*16 + k]
    __shared__ float Bs[2][16 * 128];   // [buf][k*128 + col]

    int tid = threadIdx.x;
    int row0 = blockIdx.x * 128;
    int tr = tid >> 4;       // 0..31 row group (4 rows each)
    int tc = tid & 15;       // 0..15 col group (cols tc*2 + j*32)

    unsigned int as_addr = (unsigned int)__cvta_generic_to_shared(&As[0][0]);
    unsigned int bs_addr = (unsigned int)__cvta_generic_to_shared(&Bs[0][0]);

    // per-thread staging assignment (one 16B chunk of A, one of B per tile)
    int arow = tid >> 2, ac4 = (tid & 3) << 2;        // A: row 0..127, col4
    int bkr = tid >> 5, bc8 = (tid & 31) << 2;        // B: k 0..15, col4
    int agrow = row0 + arow;
    int abytes = (agrow < NN) ? 16 : 0;
    const float* asrc_base = x + (unsigned)min(agrow, NN - 1) * 128 + ac4;
    unsigned int adst_base = as_addr + (arow * 16 + ac4) * 4;
    const float* bsrc_base = W + bkr * 128 + bc8;
    unsigned int bdst_base = bs_addr + (bkr * 128 + bc8) * 4;

    unsigned long long acc[4][4];
#pragma unroll
    for (int i = 0; i < 4; i++)
#pragma unroll
        for (int j = 0; j < 4; j++) acc[i][j] = 0ULL;

    // prefetch tile 0
    cpasync16(adst_base, asrc_base, abytes);
    cpasync16(bdst_base, bsrc_base, 16);
    cpasync_commit();

    for (int ti = 0; ti < 8; ti++) {
        int buf = ti & 1;
        if (ti < 7) {
            int nbuf = buf ^ 1;
            cpasync16(adst_base + nbuf * 128 * 16 * 4, asrc_base + (ti + 1) * 16, abytes);
            cpasync16(bdst_base + nbuf * 16 * 128 * 4, bsrc_base + (ti + 1) * 16 * 128, 16);
            cpasync_commit();
            asm volatile("cp.async.wait_group 1;");
        } else {
            asm volatile("cp.async.wait_group 0;");
        }
        __syncthreads();
        const float* Af = &As[buf][0];
        const float* Bf = &Bs[buf][0];
#pragma unroll
        for (int kk = 0; kk < 16; kk++) {
            unsigned long long b2[4];
#pragma unroll
            for (int j = 0; j < 4; j++)
                b2[j] = *(const unsigned long long*)&Bf[kk * 128 + tc * 2 + j * 32];
#pragma unroll
            for (int i = 0; i < 4; i++) {
                float a = Af[(tr * 4 + i) * 16 + kk];
                unsigned long long a2;
                asm("mov.b64 %0, {%1, %2};" : "=l"(a2) : "f"(a), "f"(a));
#pragma unroll
                for (int j = 0; j < 4; j++) acc[i][j] = ffma2(a2, b2[j], acc[i][j]);
            }
        }
        __syncthreads();
    }

    // store features (fp32)
#pragma unroll
    for (int i = 0; i < 4; i++) {
        int grow = row0 + tr * 4 + i;
        if (grow < NN) {
#pragma unroll
            for (int j = 0; j < 4; j++)
                *(unsigned long long*)&g_feat1[grow * 128 + tc * 2 + j * 32] = acc[i][j];
        }
    }

    // coef epilogue: head == j. Partial dots, reduce over tc (xor 1,2,4,8).
#pragma unroll
    for (int j = 0; j < 4; j++) {
        float alo = al1[j * 32 + tc * 2], ahi = al1[j * 32 + tc * 2 + 1];
        float rlo = ar1[j * 32 + tc * 2], rhi = ar1[j * 32 + tc * 2 + 1];
        float pe[4], pr[4];
#pragma unroll
        for (int i = 0; i < 4; i++) {
            float lo, hi;
            asm("mov.b64 {%0, %1}, %2;" : "=f"(lo), "=f"(hi) : "l"(acc[i][j]));
            pe[i] = lo * alo + hi * ahi;
            pr[i] = lo * rlo + hi * rhi;
        }
#pragma unroll
        for (int o = 1; o <= 8; o <<= 1) {
#pragma unroll
            for (int i = 0; i < 4; i++) {
                pe[i] += __shfl_xor_sync(0xffffffffu, pe[i], o);
                pr[i] += __shfl_xor_sync(0xffffffffu, pr[i], o);
            }
        }
        if (tc == 0) {
#pragma unroll
            for (int i = 0; i < 4; i++) {
                int grow = row0 + tr * 4 + i;
                if (grow < NN) {
                    g_el1[grow * 4 + j] = pe[i];
                    g_er1[grow * 4 + j] = pr[i];
                }
            }
        }
    }
}

// ---------------- layer 1 node aggregation + fused GEMM2/coef2 ------------
// WARP PER NODE, all 4 heads simultaneously; lane = h*8 + fq.
// Tail: mean+relu -> h[32] in smem -> 32x16 matvec (W2) -> feat2/el2/er2.
__global__ void __launch_bounds__(256, 5) node1_kernel(const float* __restrict__ b1,
                                                       const float* __restrict__ W2,
                                                       const float* __restrict__ al2,
                                                       const float* __restrict__ ar2) {
    __shared__ float sW2[512];
    __shared__ int   sh_src[8][32];
    __shared__ float sh_w[8][4][32];
    __shared__ float sh_h[8][32];

    for (int i = threadIdx.x; i < 512; i += 256) sW2[i] = W2[i];
    __syncthreads();

    int wid = threadIdx.x >> 5;
    int lane = threadIdx.x & 31;
    int n = blockIdx.x * 8 + wid;
    if (n >= NN) return;
    int h = lane >> 3;

    int beg = g_rowptr[n], deg = g_rowptr[n + 1] - beg;
    float4 ern = *(const float4*)&g_er1[n * 4];

    float4 dsum = make_float4(0.f, 0.f, 0.f, 0.f);
    float4 acc  = make_float4(0.f, 0.f, 0.f, 0.f);

    for (int c0 = 0; c0 < deg; c0 += 32) {
        int cnt = min(deg - c0, 32);
        if (lane < cnt) {
            int s = g_csrsrc[beg + c0 + lane];
            sh_src[wid][lane] = s;
            float4 el = *(const float4*)&g_el1[s * 4];
            float e0 = el.x + ern.x; e0 = (e0 > 0.f) ? e0 : 0.2f * e0;
            float e1 = el.y + ern.y; e1 = (e1 > 0.f) ? e1 : 0.2f * e1;
            float e2 = el.z + ern.z; e2 = (e2 > 0.f) ? e2 : 0.2f * e2;
            float e3 = el.w + ern.w; e3 = (e3 > 0.f) ? e3 : 0.2f * e3;
            float w0 = __expf(e0), w1 = __expf(e1), w2 = __expf(e2), w3 = __expf(e3);
            dsum.x += w0; dsum.y += w1; dsum.z += w2; dsum.w += w3;
            sh_w[wid][0][lane] = w0; sh_w[wid][1][lane] = w1;
            sh_w[wid][2][lane] = w2; sh_w[wid][3][lane] = w3;
        }
        __syncwarp();
        int e = 0;
        for (; e + 4 <= cnt; e += 4) {
            int s0 = sh_src[wid][e],     s1 = sh_src[wid][e + 1];
            int s2 = sh_src[wid][e + 2], s3 = sh_src[wid][e + 3];
            float w0 = sh_w[wid][h][e],     w1 = sh_w[wid][h][e + 1];
            float w2 = sh_w[wid][h][e + 2], w3 = sh_w[wid][h][e + 3];
            float4 f0 = *(const float4*)&g_feat1[s0 * 128 + lane * 4];
            float4 f1 = *(const float4*)&g_feat1[s1 * 128 + lane * 4];
            float4 f2 = *(const float4*)&g_feat1[s2 * 128 + lane * 4];
            float4 f3 = *(const float4*)&g_feat1[s3 * 128 + lane * 4];
            acc.x = fmaf(w0, f0.x, acc.x); acc.y = fmaf(w0, f0.y, acc.y);
            acc.z = fmaf(w0, f0.z, acc.z); acc.w = fmaf(w0, f0.w, acc.w);
            acc.x = fmaf(w1, f1.x, acc.x); acc.y = fmaf(w1, f1.y, acc.y);
            acc.z = fmaf(w1, f1.z, acc.z); acc.w = fmaf(w1, f1.w, acc.w);
            acc.x = fmaf(w2, f2.x, acc.x); acc.y = fmaf(w2, f2.y, acc.y);
            acc.z = fmaf(w2, f2.z, acc.z); acc.w = fmaf(w2, f2.w, acc.w);
            acc.x = fmaf(w3, f3.x, acc.x); acc.y = fmaf(w3, f3.y, acc.y);
            acc.z = fmaf(w3, f3.z, acc.z); acc.w = fmaf(w3, f3.w, acc.w);
        }
        for (; e < cnt; e++) {
            int s = sh_src[wid][e];
            float w = sh_w[wid][h][e];
            float4 f = *(const float4*)&g_feat1[s * 128 + lane * 4];
            acc.x = fmaf(w, f.x, acc.x); acc.y = fmaf(w, f.y, acc.y);
            acc.z = fmaf(w, f.z, acc.z); acc.w = fmaf(w, f.w, acc.w);
        }
        __syncwarp();
    }

#pragma unroll
    for (int o = 16; o; o >>= 1) {
        dsum.x += __shfl_xor_sync(0xffffffffu, dsum.x, o);
        dsum.y += __shfl_xor_sync(0xffffffffu, dsum.y, o);
        dsum.z += __shfl_xor_sync(0xffffffffu, dsum.z, o);
        dsum.w += __shfl_xor_sync(0xffffffffu, dsum.w, o);
    }
    float denom = (h == 0) ? dsum.x : (h == 1) ? dsum.y : (h == 2) ? dsum.z : dsum.w;
    float inv = 1.f / ((denom == 0.f) ? 1.f : denom);

    float4 bv = ((const float4*)b1)[lane];
    float4 v;
    v.x = acc.x * inv + bv.x;
    v.y = acc.y * inv + bv.y;
    v.z = acc.z * inv + bv.z;
    v.w = acc.w * inv + bv.w;

    // mean over heads: xor 8, 16 sums the 4 head lanes at fixed fq
#pragma unroll
    for (int o = 8; o <= 16; o <<= 1) {
        v.x += __shfl_xor_sync(0xffffffffu, v.x, o);
        v.y += __shfl_xor_sync(0xffffffffu, v.y, o);
        v.z += __shfl_xor_sync(0xffffffffu, v.z, o);
        v.w += __shfl_xor_sync(0xffffffffu, v.w, o);
    }
    if (lane < 8) {
        float4 o4;
        o4.x = fmaxf(0.25f * v.x, 0.f);
        o4.y = fmaxf(0.25f * v.y, 0.f);
        o4.z = fmaxf(0.25f * v.z, 0.f);
        o4.w = fmaxf(0.25f * v.w, 0.f);
        *(float4*)&sh_h[wid][lane * 4] = o4;
    }
    __syncwarp();

    // fused GEMM2: feat2[c] = sum_k h[k]*W2[k][c]; split k over lane halves
    int p = lane >> 4, c = lane & 15;
    float a2 = 0.f;
#pragma unroll
    for (int k = 0; k < 16; k++) {
        int kk = p * 16 + k;
        a2 = fmaf(sh_h[wid][kk], sW2[kk * 16 + c], a2);
    }
    a2 += __shfl_xor_sync(0xffffffffu, a2, 16);
    if (lane < 16) {
        g_feat2[n * 16 + c] = a2;
        float pe = a2 * al2[c];
        float pr = a2 * ar2[c];
#pragma unroll
        for (int o = 1; o <= 8; o <<= 1) {
            pe += __shfl_xor_sync(0x0000ffffu, pe, o);
            pr += __shfl_xor_sync(0x0000ffffu, pr, o);
        }
        if (c == 0) { g_el2[n] = pe; g_er2[n] = pr; }
    }
}

// ---------------- layer 2 node aggregation + state cleanup ----------------
__global__ void __launch_bounds__(128) node2_kernel(const float* __restrict__ b2,
                                                    float* __restrict__ out) {
    // cleanup (state must equal BSS-zero initial condition after every call)
    int gi = blockIdx.x * 128 + threadIdx.x;
    if (gi < NN) g_cursor[gi] = 0;
    if (gi < SCAN_NB) g_desc[gi] = 0ULL;
    if (gi == 0) g_scanctr = 0;

    int wid = threadIdx.x >> 5;
    int lane = threadIdx.x & 31;
    int n = blockIdx.x * 4 + wid;
    if (n >= NN) return;
    int beg = g_rowptr[n], end = g_rowptr[n + 1];
    int deg = end - beg;
    float er_n = g_er2[n];
    int p = lane >> 4, d = lane & 15;

    float denom = 0.f, acc = 0.f;
    for (int c0 = 0; c0 < deg; c0 += 32) {
        int cnt = min(deg - c0, 32);
        int s = 0; float w = 0.f;
        if (lane < cnt) {
            s = g_csrsrc[beg + c0 + lane];
            float e = g_el2[s] + er_n;
            e = (e > 0.f) ? e : 0.2f * e;
            w = __expf(e);
            denom += w;
        }
        for (int j2 = 0; j2 < cnt; j2 += 2) {
            int j = j2 + p;
            int jj = (j < cnt) ? j : 0;
            float wj = __shfl_sync(0xffffffffu, w, jj);
            int   sj = __shfl_sync(0xffffffffu, s, jj);
            if (j < cnt) acc = fmaf(wj, g_feat2[sj * 16 + d], acc);
        }
    }
#pragma unroll
    for (int o = 16; o; o >>= 1) denom += __shfl_xor_sync(0xffffffffu, denom, o);
    acc += __shfl_down_sync(0xffffffffu, acc, 16);
    float dsafe = (denom == 0.f) ? 1.f : denom;
    if (lane < 16) out[n * 16 + lane] = acc / dsafe + b2[lane];
}

// ---------------- launch ----------------
// Launch index 3 == node1_kernel (profiler captures absolute index 3).
extern "C" void kernel_launch(void* const* d_in, const int* in_sizes, int n_in,
                              void* d_out, int out_size) {
    const float* x   = (const float*)d_in[0];
    const int*   src = (const int*)  d_in[1];
    const int*   dst = (const int*)  d_in[2];
    const float* W1  = (const float*)d_in[3];
    const float* al1 = (const float*)d_in[4];
    const float* ar1 = (const float*)d_in[5];
    const float* b1  = (const float*)d_in[6];
    const float* W2  = (const float*)d_in[7];
    const float* al2 = (const float*)d_in[8];
    const float* ar2 = (const float*)d_in[9];
    const float* b2  = (const float*)d_in[10];
    float* out = (float*)d_out;

    hist_kernel<<<(EE + 255) / 256, 256>>>(dst);                                 // 0
    scan_kernel<<<SCAN_NB, 256>>>();                                             // 1
    gemm1_scatter_kernel<<<GEMM_NB + SCAT_NB, 512>>>(x, W1, al1, ar1, src, dst); // 2
    node1_kernel<<<(NN + 7) / 8, 256>>>(b1, W2, al2, ar2);                       // 3 <-- profiled
    node2_kernel<<<(NN + 3) / 4, 128>>>(b2, out);                                // 4
}